// round 8
// baseline (speedup 1.0000x reference)
#include <cuda_runtime.h>
#include <cuda_bf16.h>
#include <cstdint>
#include <cstddef>

#define BB 16
#define IC 8
#define OC 8
#define NV 3
#define HH 256
#define WW 256
#define M1 16
#define M2 16
#define TD 256

// -------------------- static scratch (no runtime allocation) --------------------
__device__ __align__(16) float2 g_Y[BB*IC*NV*HH*16];      // fwd DFT over w
__device__ __align__(16) float2 g_X[BB*IC*NV*32*16];      // fwd modes
__device__ __align__(16) float  g_TW[4*BB*(IC*OC*NV*M1*M2)]; // time-contracted weights
__device__ __align__(16) float  g_T5c[2048];              // [kw][w]: cos * al
__device__ __align__(16) float  g_T5s[2048];              // [kw][w]: sin * al

// ---------------------------------------------------------------------------
// k0: k5-stage twiddle tables, once per launch. 8 x 256 threads.
// ---------------------------------------------------------------------------
__global__ __launch_bounds__(256) void k0_tables() {
    const int idx = blockIdx.x * 256 + threadIdx.x;    // 0..2047
    int kw = idx >> 7, w = idx & 127;
    float sn, cs;
    sincospif((float)(kw * w) * (1.0f / 128.0f), &sn, &cs);
    float al = ((kw == 0) ? 1.0f : 2.0f) * (1.0f / 65536.0f);
    g_T5c[idx] = cs * al;
    g_T5s[idx] = sn * al;
}

// ---------------------------------------------------------------------------
// k1: forward DFT over w (round-3 measured-best version).
// Parity split; incremental phasor rotation. 32 rows/block, grid 3072 x 128.
// ---------------------------------------------------------------------------
__global__ __launch_bounds__(128) void k1_fwd_w(const float* __restrict__ x) {
    __shared__ float sx[32][256];
    const int tid = threadIdx.x;

    const float4* xg = (const float4*)(x + (size_t)blockIdx.x * (32 * 256));
    float4* sx4 = (float4*)sx;
#pragma unroll
    for (int it = 0; it < 16; it++)
        sx4[it * 128 + tid] = xg[it * 128 + tid];
    __syncthreads();

#pragma unroll
    for (int p = tid; p < 4096; p += 128) {
        int r = p >> 7, w = p & 127;
        float a = sx[r][w], b = sx[r][w + 128];
        sx[r][w]       = a + b;
        sx[r][w + 128] = a - b;
    }
    __syncthreads();

    const int k  = tid & 15;
    const int rg = tid >> 4;
    const int base = (k & 1) << 7;

    float sn, cs;
    sincospif((float)k * (1.0f / 128.0f), &sn, &cs);
    const float stc = cs, sts = -sn;
    float pc = 1.0f, ps = 0.0f;

    float ar0 = 0, ai0 = 0, ar1 = 0, ai1 = 0, ar2 = 0, ai2 = 0, ar3 = 0, ai3 = 0;
#pragma unroll 4
    for (int w = 0; w < 128; w++) {
        float u0 = sx[rg     ][base + w];
        float u1 = sx[rg +  8][base + w];
        float u2 = sx[rg + 16][base + w];
        float u3 = sx[rg + 24][base + w];
        ar0 += u0 * pc; ai0 += u0 * ps;
        ar1 += u1 * pc; ai1 += u1 * ps;
        ar2 += u2 * pc; ai2 += u2 * ps;
        ar3 += u3 * pc; ai3 += u3 * ps;
        float npc = pc * stc - ps * sts;
        float nps = pc * sts + ps * stc;
        pc = npc; ps = nps;
    }

    size_t rowbase = (size_t)blockIdx.x * 32;
    g_Y[(rowbase + rg     ) * 16 + k] = make_float2(ar0, ai0);
    g_Y[(rowbase + rg +  8) * 16 + k] = make_float2(ar1, ai1);
    g_Y[(rowbase + rg + 16) * 16 + k] = make_float2(ar2, ai2);
    g_Y[(rowbase + rg + 24) * 16 + k] = make_float2(ar3, ai3);
}

// ---------------------------------------------------------------------------
// k2: forward DFT over h (round-3 version). Grid 384 x 256.
// ---------------------------------------------------------------------------
__global__ __launch_bounds__(256) void k2_fwd_h() {
    __shared__ float2 sy[4096];   // [h][kw]
    const int tid = threadIdx.x;

    const float4* yg = (const float4*)(g_Y + (size_t)blockIdx.x * 4096);
    float4* sy4 = (float4*)sy;
#pragma unroll
    for (int it = 0; it < 8; it++)
        sy4[it * 256 + tid] = yg[it * 256 + tid];
    __syncthreads();

#pragma unroll
    for (int p = tid; p < 2048; p += 256) {
        int h = p >> 4, kw = p & 15;
        float2 a = sy[h * 16 + kw], b = sy[(h + 128) * 16 + kw];
        sy[h * 16 + kw]         = make_float2(a.x + b.x, a.y + b.y);
        sy[(h + 128) * 16 + kw] = make_float2(a.x - b.x, a.y - b.y);
    }
    __syncthreads();

    const int kw = tid & 15;
    const int s  = tid >> 4;
    const int hbase = (s & 1) << 7;

    float s1, c1, s2, c2;
    sincospif((float)s * (1.0f / 128.0f), &s1, &c1);
    sincospif((float)(s - 16) * (1.0f / 128.0f), &s2, &c2);
    const float st1c = c1, st1s = -s1;
    const float st2c = c2, st2s = -s2;
    float p1c = 1, p1s = 0, p2c = 1, p2s = 0;
    float a1r = 0, a1i = 0, a2r = 0, a2i = 0;

#pragma unroll 4
    for (int h = 0; h < 128; h++) {
        float2 u = sy[(hbase + h) * 16 + kw];
        a1r += u.x * p1c - u.y * p1s;
        a1i += u.x * p1s + u.y * p1c;
        a2r += u.x * p2c - u.y * p2s;
        a2i += u.x * p2s + u.y * p2c;
        float n;
        n = p1c * st1c - p1s * st1s; p1s = p1c * st1s + p1s * st1c; p1c = n;
        n = p2c * st2c - p2s * st2s; p2s = p2c * st2s + p2s * st2c; p2c = n;
    }

    size_t ob = (size_t)blockIdx.x * 512;
    g_X[ob + s * 16 + kw]        = make_float2(a1r, a1i);
    g_X[ob + (16 + s) * 16 + kw] = make_float2(a2r, a2i);
}

// ---------------------------------------------------------------------------
// k3a: time contraction (round-3 measured-best version).
// Block: 128 threads, 4 rows/thread. Grid: (96, 4).
// ---------------------------------------------------------------------------
__global__ __launch_bounds__(128) void k3a_time(const float* __restrict__ t,
                                                const float* __restrict__ wa,
                                                const float* __restrict__ wb,
                                                const float* __restrict__ wc,
                                                const float* __restrict__ wd) {
    __shared__ float ts[256][16];
    const int tid = threadIdx.x;
#pragma unroll
    for (int j = tid; j < 4096; j += 128) {
        int b = j & 15, k = j >> 4;
        ts[k][b] = t[b * 256 + k];
    }
    __syncthreads();

    const float* W = (blockIdx.y == 0) ? wa : (blockIdx.y == 1) ? wb
                   : (blockIdx.y == 2) ? wc : wd;
    float* out = g_TW + (size_t)blockIdx.y * (16 * 49152);

    const int row0 = blockIdx.x * 512 + tid * 4;
    float acc[4][16];
#pragma unroll
    for (int r = 0; r < 4; r++)
#pragma unroll
        for (int b = 0; b < 16; b++) acc[r][b] = 0.0f;

    const float4* Wp = (const float4*)(W + (size_t)row0 * 256);

    for (int k4 = 0; k4 < 64; k4++) {
        float4 wv0 = Wp[k4];
        float4 wv1 = Wp[64 + k4];
        float4 wv2 = Wp[128 + k4];
        float4 wv3 = Wp[192 + k4];
#pragma unroll
        for (int kk = 0; kk < 4; kk++) {
            const float4* trp = (const float4*)&ts[k4 * 4 + kk][0];
            float4 ta = trp[0], tb = trp[1], tc = trp[2], td = trp[3];
            float wf[4];
            wf[0] = (kk == 0) ? wv0.x : (kk == 1) ? wv0.y : (kk == 2) ? wv0.z : wv0.w;
            wf[1] = (kk == 0) ? wv1.x : (kk == 1) ? wv1.y : (kk == 2) ? wv1.z : wv1.w;
            wf[2] = (kk == 0) ? wv2.x : (kk == 1) ? wv2.y : (kk == 2) ? wv2.z : wv2.w;
            wf[3] = (kk == 0) ? wv3.x : (kk == 1) ? wv3.y : (kk == 2) ? wv3.z : wv3.w;
#pragma unroll
            for (int r = 0; r < 4; r++) {
                acc[r][0]  += wf[r] * ta.x; acc[r][1]  += wf[r] * ta.y;
                acc[r][2]  += wf[r] * ta.z; acc[r][3]  += wf[r] * ta.w;
                acc[r][4]  += wf[r] * tb.x; acc[r][5]  += wf[r] * tb.y;
                acc[r][6]  += wf[r] * tb.z; acc[r][7]  += wf[r] * tb.w;
                acc[r][8]  += wf[r] * tc.x; acc[r][9]  += wf[r] * tc.y;
                acc[r][10] += wf[r] * tc.z; acc[r][11] += wf[r] * tc.w;
                acc[r][12] += wf[r] * td.x; acc[r][13] += wf[r] * td.y;
                acc[r][14] += wf[r] * td.z; acc[r][15] += wf[r] * td.w;
            }
        }
    }

#pragma unroll
    for (int b = 0; b < 16; b++) {
        float4 v = make_float4(acc[0][b], acc[1][b], acc[2][b], acc[3][b]);
        *(float4*)&out[(size_t)b * 49152 + row0] = v;
    }
}

// ---------------------------------------------------------------------------
// k345: fused spectral-mix (k3b) + inv-h DFT (k4) + inv-w real DFT (k5).
// One block per (b,o,v): grid 384, 512 threads.
//   A: G[s][kw] (32x16 cplx) from g_X and g_TW            -> Gs (4KB)
//   B: Z[h][kw] (256x16 cplx) via parity+phasor inv-h DFT -> Zs (35KB, padded)
//   C: out rows via table inv-w DFT (tables L1-resident from g_T5)
// ---------------------------------------------------------------------------
__global__ __launch_bounds__(512) void k345_fused(float* __restrict__ out) {
    __shared__ float2 Gs[512];          // [s][kw]
    __shared__ float2 Zs[256 * 17];     // [h][kw], row stride 17 (pad)
    const int tid = threadIdx.x;
    const int bx  = blockIdx.x;
    const int b   = bx / 24;
    const int rem = bx % 24;
    const int o   = rem / 3;
    const int v   = rem % 3;

    // ---- Stage A: spectral mixing over IC ----
    {
        const int s  = tid >> 4;      // 0..31
        const int kw = tid & 15;
        const int arrbase = (s < 16) ? 0 : 2;
        const int y = s & 15;
        const float* TR = g_TW + (size_t)(arrbase * 16 + b) * 49152;
        const float* TI = g_TW + (size_t)((arrbase + 1) * 16 + b) * 49152;

        float gr = 0.0f, gi = 0.0f;
#pragma unroll
        for (int i = 0; i < 8; i++) {
            float2 xf = g_X[((size_t)((b * 8 + i) * 3 + v) * 32 + s) * 16 + kw];
            int row = (((i * 8 + o) * 3 + v) * 16 + y) * 16 + kw;
            float wr = TR[row], wi = TI[row];
            gr += xf.x * wr - xf.y * wi;
            gi += xf.x * wi + xf.y * wr;
        }
        Gs[s * 16 + kw] = make_float2(gr, gi);
    }
    __syncthreads();

    // ---- Stage B: inverse DFT over h (parity split, phasor rotation) ----
    {
        const int h   = tid & 127;
        const int kwq = tid >> 7;     // kw quad: 4 kw per thread

        float AR[4], AI[4], BR[4], BI[4];
#pragma unroll
        for (int q = 0; q < 4; q++) { AR[q] = AI[q] = BR[q] = BI[q] = 0.0f; }

        float stc, sts;
        sincospif((float)h * (1.0f / 128.0f), &sts, &stc);   // e^{+2pi i h/256}
        float pc = 1.0f, ps = 0.0f;

#pragma unroll 1
        for (int sl = 0; sl < 32; sl++) {
            if (sl == 16) { ps = -ps; }   // kh jumps to 240 == -16
            const float2* gp = &Gs[sl * 16 + kwq * 4];
            if ((sl & 1) == 0) {
#pragma unroll
                for (int q = 0; q < 4; q++) {
                    float2 g = gp[q];
                    AR[q] += g.x * pc - g.y * ps;
                    AI[q] += g.x * ps + g.y * pc;
                }
            } else {
#pragma unroll
                for (int q = 0; q < 4; q++) {
                    float2 g = gp[q];
                    BR[q] += g.x * pc - g.y * ps;
                    BI[q] += g.x * ps + g.y * pc;
                }
            }
            float n = pc * stc - ps * sts;
            ps = pc * sts + ps * stc; pc = n;
        }

        float2* zlo = &Zs[h * 17 + kwq * 4];
        float2* zhi = &Zs[(h + 128) * 17 + kwq * 4];
#pragma unroll
        for (int q = 0; q < 4; q++) {
            zlo[q] = make_float2(AR[q] + BR[q], AI[q] + BI[q]);
            zhi[q] = make_float2(AR[q] - BR[q], AI[q] - BI[q]);
        }
    }
    __syncthreads();

    // ---- Stage C: inverse real DFT over w (parity split, global tables) ----
    float* obase = out + (size_t)((b * 8 + o) * 3 + v) * 65536;
    const int r0 = tid >> 4;     // 0..31
    const int wb = tid & 15;     // w chunk: w = wb*8 + u, u=0..7

#pragma unroll 1
    for (int it = 0; it < 8; it++) {
        const int r = it * 32 + r0;

        float A[8], B[8];
#pragma unroll
        for (int u = 0; u < 8; u++) { A[u] = 0.0f; B[u] = 0.0f; }

#pragma unroll
        for (int kwv = 0; kwv < 16; kwv++) {
            float2 z = Zs[r * 17 + kwv];
            const float4* c4p = (const float4*)&g_T5c[kwv * 128 + wb * 8];
            const float4* s4p = (const float4*)&g_T5s[kwv * 128 + wb * 8];
            float4 c0 = c4p[0], c1 = c4p[1];
            float4 s0 = s4p[0], s1 = s4p[1];
            float* T = ((kwv & 1) == 0) ? A : B;
            T[0] += z.x * c0.x - z.y * s0.x;
            T[1] += z.x * c0.y - z.y * s0.y;
            T[2] += z.x * c0.z - z.y * s0.z;
            T[3] += z.x * c0.w - z.y * s0.w;
            T[4] += z.x * c1.x - z.y * s1.x;
            T[5] += z.x * c1.y - z.y * s1.y;
            T[6] += z.x * c1.z - z.y * s1.z;
            T[7] += z.x * c1.w - z.y * s1.w;
        }

        float* orow = obase + r * 256 + wb * 8;
        float4 lo0 = make_float4(A[0] + B[0], A[1] + B[1], A[2] + B[2], A[3] + B[3]);
        float4 lo1 = make_float4(A[4] + B[4], A[5] + B[5], A[6] + B[6], A[7] + B[7]);
        float4 hi0 = make_float4(A[0] - B[0], A[1] - B[1], A[2] - B[2], A[3] - B[3]);
        float4 hi1 = make_float4(A[4] - B[4], A[5] - B[5], A[6] - B[6], A[7] - B[7]);
        *(float4*)&orow[0]       = lo0;
        *(float4*)&orow[4]       = lo1;
        *(float4*)&orow[128]     = hi0;
        *(float4*)&orow[132]     = hi1;
    }
}

// ---------------------------------------------------------------------------
extern "C" void kernel_launch(void* const* d_in, const int* in_sizes, int n_in,
                              void* d_out, int out_size) {
    const float* t = nullptr;
    const float* x = nullptr;
    const float* w[4] = {nullptr, nullptr, nullptr, nullptr};
    int wn = 0;
    for (int i = 0; i < n_in; i++) {
        if (in_sizes[i] == BB * TD)                      t = (const float*)d_in[i];
        else if (in_sizes[i] == BB * IC * NV * HH * WW)  x = (const float*)d_in[i];
        else if (wn < 4)                                 w[wn++] = (const float*)d_in[i];
    }
    float* out = (float*)d_out;

    k0_tables<<<8, 256>>>();
    k1_fwd_w<<<3072, 128>>>(x);
    k2_fwd_h<<<384, 256>>>();
    k3a_time<<<dim3(96, 4), 128>>>(t, w[0], w[1], w[2], w[3]);
    k345_fused<<<384, 512>>>(out);
}

// round 9
// speedup vs baseline: 1.4476x; 1.4476x over previous
#include <cuda_runtime.h>
#include <cuda_bf16.h>
#include <cstdint>
#include <cstddef>

#define BB 16
#define IC 8
#define OC 8
#define NV 3
#define HH 256
#define WW 256
#define M1 16
#define M2 16
#define TD 256

// -------------------- static scratch (no runtime allocation) --------------------
__device__ __align__(16) float2 g_Y[BB*IC*NV*HH*16];      // fwd DFT over w
__device__ __align__(16) float2 g_X[BB*IC*NV*32*16];      // fwd modes
__device__ __align__(16) float  g_TW[4*BB*(IC*OC*NV*M1*M2)]; // time-contracted weights
__device__ __align__(16) float2 g_G[BB*OC*NV*32*16];      // mixed modes
__device__ __align__(16) float2 g_Z[BB*OC*NV*HH*16];      // inv DFT over h
__device__ __align__(16) float  g_T5c[2048];              // [kw][w]: cos * al
__device__ __align__(16) float  g_T5s[2048];              // [kw][w]: sin * al

// ---------------------------------------------------------------------------
// k0: k5-stage twiddle tables, once per launch. 8 x 256 threads.
// ---------------------------------------------------------------------------
__global__ __launch_bounds__(256) void k0_tables() {
    const int idx = blockIdx.x * 256 + threadIdx.x;    // 0..2047
    int kw = idx >> 7, w = idx & 127;
    float sn, cs;
    sincospif((float)(kw * w) * (1.0f / 128.0f), &sn, &cs);
    float al = ((kw == 0) ? 1.0f : 2.0f) * (1.0f / 65536.0f);
    g_T5c[idx] = cs * al;
    g_T5s[idx] = sn * al;
}

// ---------------------------------------------------------------------------
// k1: forward DFT over w (round-3 measured-best version, UNCHANGED).
// ---------------------------------------------------------------------------
__global__ __launch_bounds__(128) void k1_fwd_w(const float* __restrict__ x) {
    __shared__ float sx[32][256];
    const int tid = threadIdx.x;

    const float4* xg = (const float4*)(x + (size_t)blockIdx.x * (32 * 256));
    float4* sx4 = (float4*)sx;
#pragma unroll
    for (int it = 0; it < 16; it++)
        sx4[it * 128 + tid] = xg[it * 128 + tid];
    __syncthreads();

#pragma unroll
    for (int p = tid; p < 4096; p += 128) {
        int r = p >> 7, w = p & 127;
        float a = sx[r][w], b = sx[r][w + 128];
        sx[r][w]       = a + b;
        sx[r][w + 128] = a - b;
    }
    __syncthreads();

    const int k  = tid & 15;
    const int rg = tid >> 4;
    const int base = (k & 1) << 7;

    float sn, cs;
    sincospif((float)k * (1.0f / 128.0f), &sn, &cs);
    const float stc = cs, sts = -sn;
    float pc = 1.0f, ps = 0.0f;

    float ar0 = 0, ai0 = 0, ar1 = 0, ai1 = 0, ar2 = 0, ai2 = 0, ar3 = 0, ai3 = 0;
#pragma unroll 4
    for (int w = 0; w < 128; w++) {
        float u0 = sx[rg     ][base + w];
        float u1 = sx[rg +  8][base + w];
        float u2 = sx[rg + 16][base + w];
        float u3 = sx[rg + 24][base + w];
        ar0 += u0 * pc; ai0 += u0 * ps;
        ar1 += u1 * pc; ai1 += u1 * ps;
        ar2 += u2 * pc; ai2 += u2 * ps;
        ar3 += u3 * pc; ai3 += u3 * ps;
        float npc = pc * stc - ps * sts;
        float nps = pc * sts + ps * stc;
        pc = npc; ps = nps;
    }

    size_t rowbase = (size_t)blockIdx.x * 32;
    g_Y[(rowbase + rg     ) * 16 + k] = make_float2(ar0, ai0);
    g_Y[(rowbase + rg +  8) * 16 + k] = make_float2(ar1, ai1);
    g_Y[(rowbase + rg + 16) * 16 + k] = make_float2(ar2, ai2);
    g_Y[(rowbase + rg + 24) * 16 + k] = make_float2(ar3, ai3);
}

// ---------------------------------------------------------------------------
// k2: forward DFT over h (round-3 version, UNCHANGED). Grid 384 x 256.
// ---------------------------------------------------------------------------
__global__ __launch_bounds__(256) void k2_fwd_h() {
    __shared__ float2 sy[4096];   // [h][kw]
    const int tid = threadIdx.x;

    const float4* yg = (const float4*)(g_Y + (size_t)blockIdx.x * 4096);
    float4* sy4 = (float4*)sy;
#pragma unroll
    for (int it = 0; it < 8; it++)
        sy4[it * 256 + tid] = yg[it * 256 + tid];
    __syncthreads();

#pragma unroll
    for (int p = tid; p < 2048; p += 256) {
        int h = p >> 4, kw = p & 15;
        float2 a = sy[h * 16 + kw], b = sy[(h + 128) * 16 + kw];
        sy[h * 16 + kw]         = make_float2(a.x + b.x, a.y + b.y);
        sy[(h + 128) * 16 + kw] = make_float2(a.x - b.x, a.y - b.y);
    }
    __syncthreads();

    const int kw = tid & 15;
    const int s  = tid >> 4;
    const int hbase = (s & 1) << 7;

    float s1, c1, s2, c2;
    sincospif((float)s * (1.0f / 128.0f), &s1, &c1);
    sincospif((float)(s - 16) * (1.0f / 128.0f), &s2, &c2);
    const float st1c = c1, st1s = -s1;
    const float st2c = c2, st2s = -s2;
    float p1c = 1, p1s = 0, p2c = 1, p2s = 0;
    float a1r = 0, a1i = 0, a2r = 0, a2i = 0;

#pragma unroll 4
    for (int h = 0; h < 128; h++) {
        float2 u = sy[(hbase + h) * 16 + kw];
        a1r += u.x * p1c - u.y * p1s;
        a1i += u.x * p1s + u.y * p1c;
        a2r += u.x * p2c - u.y * p2s;
        a2i += u.x * p2s + u.y * p2c;
        float n;
        n = p1c * st1c - p1s * st1s; p1s = p1c * st1s + p1s * st1c; p1c = n;
        n = p2c * st2c - p2s * st2s; p2s = p2c * st2s + p2s * st2c; p2c = n;
    }

    size_t ob = (size_t)blockIdx.x * 512;
    g_X[ob + s * 16 + kw]        = make_float2(a1r, a1i);
    g_X[ob + (16 + s) * 16 + kw] = make_float2(a2r, a2i);
}

// ---------------------------------------------------------------------------
// k3a: time contraction (round-3 measured-best version, UNCHANGED).
// ---------------------------------------------------------------------------
__global__ __launch_bounds__(128) void k3a_time(const float* __restrict__ t,
                                                const float* __restrict__ wa,
                                                const float* __restrict__ wb,
                                                const float* __restrict__ wc,
                                                const float* __restrict__ wd) {
    __shared__ float ts[256][16];
    const int tid = threadIdx.x;
#pragma unroll
    for (int j = tid; j < 4096; j += 128) {
        int b = j & 15, k = j >> 4;
        ts[k][b] = t[b * 256 + k];
    }
    __syncthreads();

    const float* W = (blockIdx.y == 0) ? wa : (blockIdx.y == 1) ? wb
                   : (blockIdx.y == 2) ? wc : wd;
    float* out = g_TW + (size_t)blockIdx.y * (16 * 49152);

    const int row0 = blockIdx.x * 512 + tid * 4;
    float acc[4][16];
#pragma unroll
    for (int r = 0; r < 4; r++)
#pragma unroll
        for (int b = 0; b < 16; b++) acc[r][b] = 0.0f;

    const float4* Wp = (const float4*)(W + (size_t)row0 * 256);

    for (int k4 = 0; k4 < 64; k4++) {
        float4 wv0 = Wp[k4];
        float4 wv1 = Wp[64 + k4];
        float4 wv2 = Wp[128 + k4];
        float4 wv3 = Wp[192 + k4];
#pragma unroll
        for (int kk = 0; kk < 4; kk++) {
            const float4* trp = (const float4*)&ts[k4 * 4 + kk][0];
            float4 ta = trp[0], tb = trp[1], tc = trp[2], td = trp[3];
            float wf[4];
            wf[0] = (kk == 0) ? wv0.x : (kk == 1) ? wv0.y : (kk == 2) ? wv0.z : wv0.w;
            wf[1] = (kk == 0) ? wv1.x : (kk == 1) ? wv1.y : (kk == 2) ? wv1.z : wv1.w;
            wf[2] = (kk == 0) ? wv2.x : (kk == 1) ? wv2.y : (kk == 2) ? wv2.z : wv2.w;
            wf[3] = (kk == 0) ? wv3.x : (kk == 1) ? wv3.y : (kk == 2) ? wv3.z : wv3.w;
#pragma unroll
            for (int r = 0; r < 4; r++) {
                acc[r][0]  += wf[r] * ta.x; acc[r][1]  += wf[r] * ta.y;
                acc[r][2]  += wf[r] * ta.z; acc[r][3]  += wf[r] * ta.w;
                acc[r][4]  += wf[r] * tb.x; acc[r][5]  += wf[r] * tb.y;
                acc[r][6]  += wf[r] * tb.z; acc[r][7]  += wf[r] * tb.w;
                acc[r][8]  += wf[r] * tc.x; acc[r][9]  += wf[r] * tc.y;
                acc[r][10] += wf[r] * tc.z; acc[r][11] += wf[r] * tc.w;
                acc[r][12] += wf[r] * td.x; acc[r][13] += wf[r] * td.y;
                acc[r][14] += wf[r] * td.z; acc[r][15] += wf[r] * td.w;
            }
        }
    }

#pragma unroll
    for (int b = 0; b < 16; b++) {
        float4 v = make_float4(acc[0][b], acc[1][b], acc[2][b], acc[3][b]);
        *(float4*)&out[(size_t)b * 49152 + row0] = v;
    }
}

// ---------------------------------------------------------------------------
// k3b: spectral mixing over IC (round-3 version, UNCHANGED). Grid: 768 x 256.
// ---------------------------------------------------------------------------
__global__ __launch_bounds__(256) void k3b_mix() {
    const int gtid = blockIdx.x * 256 + threadIdx.x;
    const int kw = gtid & 15;
    int r = gtid >> 4;
    const int s = r & 31; r >>= 5;
    const int v = r % 3;  r /= 3;
    const int o = r & 7;
    const int b = r >> 3;

    const int arrbase = (s < 16) ? 0 : 2;
    const int y = s & 15;
    const float* TR = g_TW + (size_t)(arrbase * 16 + b) * 49152;
    const float* TI = g_TW + (size_t)((arrbase + 1) * 16 + b) * 49152;

    float gr = 0.0f, gi = 0.0f;
#pragma unroll
    for (int i = 0; i < 8; i++) {
        float2 xf = g_X[((size_t)((b * 8 + i) * 3 + v) * 32 + s) * 16 + kw];
        int row = (((i * 8 + o) * 3 + v) * 16 + y) * 16 + kw;
        float wr = TR[row], wi = TI[row];
        gr += xf.x * wr - xf.y * wi;
        gi += xf.x * wi + xf.y * wr;
    }
    g_G[gtid] = make_float2(gr, gi);
}

// ---------------------------------------------------------------------------
// k4: inverse DFT over h — r5 phasor-parity version (passed in r5/r6).
// Thread (h = tid&127, half = tid>>7) produces Z[h], Z[h+128] for 8 kw.
// 1 sincospif/thread; conj jump at the kh=240 boundary. Grid: 384 x 256.
// ---------------------------------------------------------------------------
__global__ __launch_bounds__(256) void k4_inv_h() {
    __shared__ float2 Gs[512];
    const int tid = threadIdx.x;
    ((float4*)Gs)[tid] = ((const float4*)(g_G + (size_t)blockIdx.x * 512))[tid];
    __syncthreads();

    const int h = tid & 127;
    const int half = tid >> 7;     // kw group: half*8 .. half*8+7

    float AR[8], AI[8], BR[8], BI[8];
#pragma unroll
    for (int q = 0; q < 8; q++) { AR[q] = AI[q] = BR[q] = BI[q] = 0.0f; }

    float stc, sts;
    sincospif((float)h * (1.0f / 128.0f), &sts, &stc);   // step = e^{+2pi i h/256}
    float pc = 1.0f, ps = 0.0f;

#pragma unroll 1
    for (int sl = 0; sl < 32; sl++) {
        if (sl == 16) { ps = -ps; }   // p = e^{i16h} -> conj -> e^{-i16h} (kh=240)
        const float4* gp = (const float4*)&Gs[sl * 16 + half * 8];
        if ((sl & 1) == 0) {
#pragma unroll
            for (int q4 = 0; q4 < 4; q4++) {
                float4 g = gp[q4];
                AR[2*q4]   += g.x * pc - g.y * ps;
                AI[2*q4]   += g.x * ps + g.y * pc;
                AR[2*q4+1] += g.z * pc - g.w * ps;
                AI[2*q4+1] += g.z * ps + g.w * pc;
            }
        } else {
#pragma unroll
            for (int q4 = 0; q4 < 4; q4++) {
                float4 g = gp[q4];
                BR[2*q4]   += g.x * pc - g.y * ps;
                BI[2*q4]   += g.x * ps + g.y * pc;
                BR[2*q4+1] += g.z * pc - g.w * ps;
                BI[2*q4+1] += g.z * ps + g.w * pc;
            }
        }
        float n = pc * stc - ps * sts;
        ps = pc * sts + ps * stc; pc = n;
    }

    float4* zlo = (float4*)(g_Z + (size_t)blockIdx.x * 4096 + h * 16 + half * 8);
    float4* zhi = (float4*)(g_Z + (size_t)blockIdx.x * 4096 + (h + 128) * 16 + half * 8);
#pragma unroll
    for (int q = 0; q < 4; q++) {
        zlo[q] = make_float4(AR[2*q] + BR[2*q], AI[2*q] + BI[2*q],
                             AR[2*q+1] + BR[2*q+1], AI[2*q+1] + BI[2*q+1]);
        zhi[q] = make_float4(AR[2*q] - BR[2*q], AI[2*q] - BI[2*q],
                             AR[2*q+1] - BR[2*q+1], AI[2*q+1] - BI[2*q+1]);
    }
}

// ---------------------------------------------------------------------------
// k5: inverse real DFT over w — r3 math/layout, tables STAGED from g_T5
// (instead of 2048 sincospif per block). Passed in r5. Grid: 3072 x 256.
// ---------------------------------------------------------------------------
__global__ __launch_bounds__(256) void k5_inv_w(float* __restrict__ out) {
    __shared__ float Ct[16 * 128];
    __shared__ float St[16 * 128];
    __shared__ float2 Zs[512];
    const int tid = threadIdx.x;

    {
        float4* c4 = (float4*)Ct; const float4* gc = (const float4*)g_T5c;
        float4* s4 = (float4*)St; const float4* gs = (const float4*)g_T5s;
#pragma unroll
        for (int j = 0; j < 2; j++) {
            c4[j * 256 + tid] = gc[j * 256 + tid];
            s4[j * 256 + tid] = gs[j * 256 + tid];
        }
    }
    ((float4*)Zs)[tid] = ((const float4*)(g_Z + (size_t)blockIdx.x * 512))[tid];
    __syncthreads();

    const int r  = tid >> 3;
    const int wb = tid & 7;

    float A[16], B[16];
#pragma unroll
    for (int u = 0; u < 16; u++) { A[u] = 0.0f; B[u] = 0.0f; }

#pragma unroll
    for (int kwv = 0; kwv < 16; kwv++) {
        float2 z = Zs[r * 16 + kwv];
#pragma unroll
        for (int u4 = 0; u4 < 4; u4++) {
            float4 c4 = *(const float4*)&Ct[kwv * 128 + wb * 16 + u4 * 4];
            float4 s4 = *(const float4*)&St[kwv * 128 + wb * 16 + u4 * 4];
            float* T = ((kwv & 1) == 0) ? A : B;
            T[u4 * 4 + 0] += z.x * c4.x - z.y * s4.x;
            T[u4 * 4 + 1] += z.x * c4.y - z.y * s4.y;
            T[u4 * 4 + 2] += z.x * c4.z - z.y * s4.z;
            T[u4 * 4 + 3] += z.x * c4.w - z.y * s4.w;
        }
    }

    float* orow = out + (size_t)blockIdx.x * (32 * 256) + r * 256 + wb * 16;
#pragma unroll
    for (int u4 = 0; u4 < 4; u4++) {
        float4 lo = make_float4(A[u4*4+0] + B[u4*4+0], A[u4*4+1] + B[u4*4+1],
                                A[u4*4+2] + B[u4*4+2], A[u4*4+3] + B[u4*4+3]);
        float4 hi = make_float4(A[u4*4+0] - B[u4*4+0], A[u4*4+1] - B[u4*4+1],
                                A[u4*4+2] - B[u4*4+2], A[u4*4+3] - B[u4*4+3]);
        *(float4*)&orow[u4 * 4]       = lo;
        *(float4*)&orow[128 + u4 * 4] = hi;
    }
}

// ---------------------------------------------------------------------------
extern "C" void kernel_launch(void* const* d_in, const int* in_sizes, int n_in,
                              void* d_out, int out_size) {
    const float* t = nullptr;
    const float* x = nullptr;
    const float* w[4] = {nullptr, nullptr, nullptr, nullptr};
    int wn = 0;
    for (int i = 0; i < n_in; i++) {
        if (in_sizes[i] == BB * TD)                      t = (const float*)d_in[i];
        else if (in_sizes[i] == BB * IC * NV * HH * WW)  x = (const float*)d_in[i];
        else if (wn < 4)                                 w[wn++] = (const float*)d_in[i];
    }
    float* out = (float*)d_out;

    k0_tables<<<8, 256>>>();
    k1_fwd_w<<<3072, 128>>>(x);
    k2_fwd_h<<<384, 256>>>();
    k3a_time<<<dim3(96, 4), 128>>>(t, w[0], w[1], w[2], w[3]);
    k3b_mix<<<768, 256>>>();
    k4_inv_h<<<384, 256>>>();
    k5_inv_w<<<3072, 256>>>(out);
}

// round 10
// speedup vs baseline: 1.4566x; 1.0062x over previous
#include <cuda_runtime.h>
#include <cuda_bf16.h>
#include <cstdint>
#include <cstddef>

#define BB 16
#define IC 8
#define OC 8
#define NV 3
#define HH 256
#define WW 256
#define M1 16
#define M2 16
#define TD 256

// -------------------- static scratch (no runtime allocation) --------------------
__device__ __align__(16) float2 g_Y[BB*IC*NV*HH*16];      // fwd DFT over w
__device__ __align__(16) float2 g_X[BB*IC*NV*32*16];      // fwd modes
__device__ __align__(16) float  g_TW[4*BB*(IC*OC*NV*M1*M2)]; // time-contracted weights
__device__ __align__(16) float2 g_G[BB*OC*NV*32*16];      // mixed modes
__device__ __align__(16) float2 g_Z[BB*OC*NV*HH*16];      // inv DFT over h
__device__ __align__(16) float  g_T5c[2048];              // [kw][w]: cos * al
__device__ __align__(16) float  g_T5s[2048];              // [kw][w]: sin * al

// ---------------------------------------------------------------------------
// k0: k5-stage twiddle tables, once per launch. 8 x 256 threads.
// ---------------------------------------------------------------------------
__global__ __launch_bounds__(256) void k0_tables() {
    const int idx = blockIdx.x * 256 + threadIdx.x;    // 0..2047
    int kw = idx >> 7, w = idx & 127;
    float sn, cs;
    sincospif((float)(kw * w) * (1.0f / 128.0f), &sn, &cs);
    float al = ((kw == 0) ? 1.0f : 2.0f) * (1.0f / 65536.0f);
    g_T5c[idx] = cs * al;
    g_T5s[idx] = sn * al;
}

// ---------------------------------------------------------------------------
// k1: forward DFT over w — BANK-CONFLICT-FREE version of the r3 kernel.
// Parity (sum/diff over w vs w+128) computed during staging into two smem
// regions with row stride 132 (== 4 mod 32) and diff region offset 16 floats
// (mod 32), so the 4 addresses touched by each inner-loop LDS land in 4
// distinct banks. Math/twiddles identical to r3. 32 rows/block, grid 3072.
// ---------------------------------------------------------------------------
#define K1_STRIDE 132
#define K1_DIFOFF (32 * K1_STRIDE + 16)     // 4240; 4240 mod 32 == 16
__global__ __launch_bounds__(128) void k1_fwd_w(const float* __restrict__ x) {
    __shared__ float sbuf[K1_DIFOFF + 32 * K1_STRIDE];   // ~33.9 KB
    const int tid = threadIdx.x;

    // Stage: load both halves of each row, write sum and diff (coalesced
    // global float4 reads; contiguous STS.128 -> conflict-free).
    const float4* xg = (const float4*)(x + (size_t)blockIdx.x * (32 * 256));
#pragma unroll
    for (int j = 0; j < 8; j++) {
        int p = j * 128 + tid;           // 0..1023
        int row = p >> 5, c4 = p & 31;
        float4 a = xg[row * 64 + c4];
        float4 b = xg[row * 64 + 32 + c4];
        *(float4*)&sbuf[row * K1_STRIDE + c4 * 4] =
            make_float4(a.x + b.x, a.y + b.y, a.z + b.z, a.w + b.w);
        *(float4*)&sbuf[K1_DIFOFF + row * K1_STRIDE + c4 * 4] =
            make_float4(a.x - b.x, a.y - b.y, a.z - b.z, a.w - b.w);
    }
    __syncthreads();

    const int k  = tid & 15;
    const int rg = tid >> 4;
    // even k reads sum region, odd k reads diff region
    const float* base0 = sbuf + ((k & 1) ? K1_DIFOFF : 0) + rg * K1_STRIDE;

    float sn, cs;
    sincospif((float)k * (1.0f / 128.0f), &sn, &cs);
    const float stc = cs, sts = -sn;
    float pc = 1.0f, ps = 0.0f;

    float ar0 = 0, ai0 = 0, ar1 = 0, ai1 = 0, ar2 = 0, ai2 = 0, ar3 = 0, ai3 = 0;
#pragma unroll 4
    for (int w = 0; w < 128; w++) {
        float u0 = base0[w];
        float u1 = base0[ 8 * K1_STRIDE + w];
        float u2 = base0[16 * K1_STRIDE + w];
        float u3 = base0[24 * K1_STRIDE + w];
        ar0 += u0 * pc; ai0 += u0 * ps;
        ar1 += u1 * pc; ai1 += u1 * ps;
        ar2 += u2 * pc; ai2 += u2 * ps;
        ar3 += u3 * pc; ai3 += u3 * ps;
        float npc = pc * stc - ps * sts;
        float nps = pc * sts + ps * stc;
        pc = npc; ps = nps;
    }

    size_t rowbase = (size_t)blockIdx.x * 32;
    g_Y[(rowbase + rg     ) * 16 + k] = make_float2(ar0, ai0);
    g_Y[(rowbase + rg +  8) * 16 + k] = make_float2(ar1, ai1);
    g_Y[(rowbase + rg + 16) * 16 + k] = make_float2(ar2, ai2);
    g_Y[(rowbase + rg + 24) * 16 + k] = make_float2(ar3, ai3);
}

// ---------------------------------------------------------------------------
// k2: forward DFT over h (round-3 version, UNCHANGED). Grid 384 x 256.
// ---------------------------------------------------------------------------
__global__ __launch_bounds__(256) void k2_fwd_h() {
    __shared__ float2 sy[4096];   // [h][kw]
    const int tid = threadIdx.x;

    const float4* yg = (const float4*)(g_Y + (size_t)blockIdx.x * 4096);
    float4* sy4 = (float4*)sy;
#pragma unroll
    for (int it = 0; it < 8; it++)
        sy4[it * 256 + tid] = yg[it * 256 + tid];
    __syncthreads();

#pragma unroll
    for (int p = tid; p < 2048; p += 256) {
        int h = p >> 4, kw = p & 15;
        float2 a = sy[h * 16 + kw], b = sy[(h + 128) * 16 + kw];
        sy[h * 16 + kw]         = make_float2(a.x + b.x, a.y + b.y);
        sy[(h + 128) * 16 + kw] = make_float2(a.x - b.x, a.y - b.y);
    }
    __syncthreads();

    const int kw = tid & 15;
    const int s  = tid >> 4;
    const int hbase = (s & 1) << 7;

    float s1, c1, s2, c2;
    sincospif((float)s * (1.0f / 128.0f), &s1, &c1);
    sincospif((float)(s - 16) * (1.0f / 128.0f), &s2, &c2);
    const float st1c = c1, st1s = -s1;
    const float st2c = c2, st2s = -s2;
    float p1c = 1, p1s = 0, p2c = 1, p2s = 0;
    float a1r = 0, a1i = 0, a2r = 0, a2i = 0;

#pragma unroll 4
    for (int h = 0; h < 128; h++) {
        float2 u = sy[(hbase + h) * 16 + kw];
        a1r += u.x * p1c - u.y * p1s;
        a1i += u.x * p1s + u.y * p1c;
        a2r += u.x * p2c - u.y * p2s;
        a2i += u.x * p2s + u.y * p2c;
        float n;
        n = p1c * st1c - p1s * st1s; p1s = p1c * st1s + p1s * st1c; p1c = n;
        n = p2c * st2c - p2s * st2s; p2s = p2c * st2s + p2s * st2c; p2c = n;
    }

    size_t ob = (size_t)blockIdx.x * 512;
    g_X[ob + s * 16 + kw]        = make_float2(a1r, a1i);
    g_X[ob + (16 + s) * 16 + kw] = make_float2(a2r, a2i);
}

// ---------------------------------------------------------------------------
// k3a: time contraction (round-3 measured-best version, UNCHANGED).
// ---------------------------------------------------------------------------
__global__ __launch_bounds__(128) void k3a_time(const float* __restrict__ t,
                                                const float* __restrict__ wa,
                                                const float* __restrict__ wb,
                                                const float* __restrict__ wc,
                                                const float* __restrict__ wd) {
    __shared__ float ts[256][16];
    const int tid = threadIdx.x;
#pragma unroll
    for (int j = tid; j < 4096; j += 128) {
        int b = j & 15, k = j >> 4;
        ts[k][b] = t[b * 256 + k];
    }
    __syncthreads();

    const float* W = (blockIdx.y == 0) ? wa : (blockIdx.y == 1) ? wb
                   : (blockIdx.y == 2) ? wc : wd;
    float* out = g_TW + (size_t)blockIdx.y * (16 * 49152);

    const int row0 = blockIdx.x * 512 + tid * 4;
    float acc[4][16];
#pragma unroll
    for (int r = 0; r < 4; r++)
#pragma unroll
        for (int b = 0; b < 16; b++) acc[r][b] = 0.0f;

    const float4* Wp = (const float4*)(W + (size_t)row0 * 256);

    for (int k4 = 0; k4 < 64; k4++) {
        float4 wv0 = Wp[k4];
        float4 wv1 = Wp[64 + k4];
        float4 wv2 = Wp[128 + k4];
        float4 wv3 = Wp[192 + k4];
#pragma unroll
        for (int kk = 0; kk < 4; kk++) {
            const float4* trp = (const float4*)&ts[k4 * 4 + kk][0];
            float4 ta = trp[0], tb = trp[1], tc = trp[2], td = trp[3];
            float wf[4];
            wf[0] = (kk == 0) ? wv0.x : (kk == 1) ? wv0.y : (kk == 2) ? wv0.z : wv0.w;
            wf[1] = (kk == 0) ? wv1.x : (kk == 1) ? wv1.y : (kk == 2) ? wv1.z : wv1.w;
            wf[2] = (kk == 0) ? wv2.x : (kk == 1) ? wv2.y : (kk == 2) ? wv2.z : wv2.w;
            wf[3] = (kk == 0) ? wv3.x : (kk == 1) ? wv3.y : (kk == 2) ? wv3.z : wv3.w;
#pragma unroll
            for (int r = 0; r < 4; r++) {
                acc[r][0]  += wf[r] * ta.x; acc[r][1]  += wf[r] * ta.y;
                acc[r][2]  += wf[r] * ta.z; acc[r][3]  += wf[r] * ta.w;
                acc[r][4]  += wf[r] * tb.x; acc[r][5]  += wf[r] * tb.y;
                acc[r][6]  += wf[r] * tb.z; acc[r][7]  += wf[r] * tb.w;
                acc[r][8]  += wf[r] * tc.x; acc[r][9]  += wf[r] * tc.y;
                acc[r][10] += wf[r] * tc.z; acc[r][11] += wf[r] * tc.w;
                acc[r][12] += wf[r] * td.x; acc[r][13] += wf[r] * td.y;
                acc[r][14] += wf[r] * td.z; acc[r][15] += wf[r] * td.w;
            }
        }
    }

#pragma unroll
    for (int b = 0; b < 16; b++) {
        float4 v = make_float4(acc[0][b], acc[1][b], acc[2][b], acc[3][b]);
        *(float4*)&out[(size_t)b * 49152 + row0] = v;
    }
}

// ---------------------------------------------------------------------------
// k3b: spectral mixing over IC (round-3 version, UNCHANGED). Grid: 768 x 256.
// ---------------------------------------------------------------------------
__global__ __launch_bounds__(256) void k3b_mix() {
    const int gtid = blockIdx.x * 256 + threadIdx.x;
    const int kw = gtid & 15;
    int r = gtid >> 4;
    const int s = r & 31; r >>= 5;
    const int v = r % 3;  r /= 3;
    const int o = r & 7;
    const int b = r >> 3;

    const int arrbase = (s < 16) ? 0 : 2;
    const int y = s & 15;
    const float* TR = g_TW + (size_t)(arrbase * 16 + b) * 49152;
    const float* TI = g_TW + (size_t)((arrbase + 1) * 16 + b) * 49152;

    float gr = 0.0f, gi = 0.0f;
#pragma unroll
    for (int i = 0; i < 8; i++) {
        float2 xf = g_X[((size_t)((b * 8 + i) * 3 + v) * 32 + s) * 16 + kw];
        int row = (((i * 8 + o) * 3 + v) * 16 + y) * 16 + kw;
        float wr = TR[row], wi = TI[row];
        gr += xf.x * wr - xf.y * wi;
        gi += xf.x * wi + xf.y * wr;
    }
    g_G[gtid] = make_float2(gr, gi);
}

// ---------------------------------------------------------------------------
// k4: inverse DFT over h — r5 phasor-parity version (UNCHANGED from r9).
// ---------------------------------------------------------------------------
__global__ __launch_bounds__(256) void k4_inv_h() {
    __shared__ float2 Gs[512];
    const int tid = threadIdx.x;
    ((float4*)Gs)[tid] = ((const float4*)(g_G + (size_t)blockIdx.x * 512))[tid];
    __syncthreads();

    const int h = tid & 127;
    const int half = tid >> 7;     // kw group: half*8 .. half*8+7

    float AR[8], AI[8], BR[8], BI[8];
#pragma unroll
    for (int q = 0; q < 8; q++) { AR[q] = AI[q] = BR[q] = BI[q] = 0.0f; }

    float stc, sts;
    sincospif((float)h * (1.0f / 128.0f), &sts, &stc);   // step = e^{+2pi i h/256}
    float pc = 1.0f, ps = 0.0f;

#pragma unroll 1
    for (int sl = 0; sl < 32; sl++) {
        if (sl == 16) { ps = -ps; }   // p = e^{i16h} -> conj -> e^{-i16h} (kh=240)
        const float4* gp = (const float4*)&Gs[sl * 16 + half * 8];
        if ((sl & 1) == 0) {
#pragma unroll
            for (int q4 = 0; q4 < 4; q4++) {
                float4 g = gp[q4];
                AR[2*q4]   += g.x * pc - g.y * ps;
                AI[2*q4]   += g.x * ps + g.y * pc;
                AR[2*q4+1] += g.z * pc - g.w * ps;
                AI[2*q4+1] += g.z * ps + g.w * pc;
            }
        } else {
#pragma unroll
            for (int q4 = 0; q4 < 4; q4++) {
                float4 g = gp[q4];
                BR[2*q4]   += g.x * pc - g.y * ps;
                BI[2*q4]   += g.x * ps + g.y * pc;
                BR[2*q4+1] += g.z * pc - g.w * ps;
                BI[2*q4+1] += g.z * ps + g.w * pc;
            }
        }
        float n = pc * stc - ps * sts;
        ps = pc * sts + ps * stc; pc = n;
    }

    float4* zlo = (float4*)(g_Z + (size_t)blockIdx.x * 4096 + h * 16 + half * 8);
    float4* zhi = (float4*)(g_Z + (size_t)blockIdx.x * 4096 + (h + 128) * 16 + half * 8);
#pragma unroll
    for (int q = 0; q < 4; q++) {
        zlo[q] = make_float4(AR[2*q] + BR[2*q], AI[2*q] + BI[2*q],
                             AR[2*q+1] + BR[2*q+1], AI[2*q+1] + BI[2*q+1]);
        zhi[q] = make_float4(AR[2*q] - BR[2*q], AI[2*q] - BI[2*q],
                             AR[2*q+1] - BR[2*q+1], AI[2*q+1] - BI[2*q+1]);
    }
}

// ---------------------------------------------------------------------------
// k5: inverse real DFT over w — staged tables (UNCHANGED from r9). Grid 3072.
// ---------------------------------------------------------------------------
__global__ __launch_bounds__(256) void k5_inv_w(float* __restrict__ out) {
    __shared__ float Ct[16 * 128];
    __shared__ float St[16 * 128];
    __shared__ float2 Zs[512];
    const int tid = threadIdx.x;

    {
        float4* c4 = (float4*)Ct; const float4* gc = (const float4*)g_T5c;
        float4* s4 = (float4*)St; const float4* gs = (const float4*)g_T5s;
#pragma unroll
        for (int j = 0; j < 2; j++) {
            c4[j * 256 + tid] = gc[j * 256 + tid];
            s4[j * 256 + tid] = gs[j * 256 + tid];
        }
    }
    ((float4*)Zs)[tid] = ((const float4*)(g_Z + (size_t)blockIdx.x * 512))[tid];
    __syncthreads();

    const int r  = tid >> 3;
    const int wb = tid & 7;

    float A[16], B[16];
#pragma unroll
    for (int u = 0; u < 16; u++) { A[u] = 0.0f; B[u] = 0.0f; }

#pragma unroll
    for (int kwv = 0; kwv < 16; kwv++) {
        float2 z = Zs[r * 16 + kwv];
#pragma unroll
        for (int u4 = 0; u4 < 4; u4++) {
            float4 c4 = *(const float4*)&Ct[kwv * 128 + wb * 16 + u4 * 4];
            float4 s4 = *(const float4*)&St[kwv * 128 + wb * 16 + u4 * 4];
            float* T = ((kwv & 1) == 0) ? A : B;
            T[u4 * 4 + 0] += z.x * c4.x - z.y * s4.x;
            T[u4 * 4 + 1] += z.x * c4.y - z.y * s4.y;
            T[u4 * 4 + 2] += z.x * c4.z - z.y * s4.z;
            T[u4 * 4 + 3] += z.x * c4.w - z.y * s4.w;
        }
    }

    float* orow = out + (size_t)blockIdx.x * (32 * 256) + r * 256 + wb * 16;
#pragma unroll
    for (int u4 = 0; u4 < 4; u4++) {
        float4 lo = make_float4(A[u4*4+0] + B[u4*4+0], A[u4*4+1] + B[u4*4+1],
                                A[u4*4+2] + B[u4*4+2], A[u4*4+3] + B[u4*4+3]);
        float4 hi = make_float4(A[u4*4+0] - B[u4*4+0], A[u4*4+1] - B[u4*4+1],
                                A[u4*4+2] - B[u4*4+2], A[u4*4+3] - B[u4*4+3]);
        *(float4*)&orow[u4 * 4]       = lo;
        *(float4*)&orow[128 + u4 * 4] = hi;
    }
}

// ---------------------------------------------------------------------------
extern "C" void kernel_launch(void* const* d_in, const int* in_sizes, int n_in,
                              void* d_out, int out_size) {
    const float* t = nullptr;
    const float* x = nullptr;
    const float* w[4] = {nullptr, nullptr, nullptr, nullptr};
    int wn = 0;
    for (int i = 0; i < n_in; i++) {
        if (in_sizes[i] == BB * TD)                      t = (const float*)d_in[i];
        else if (in_sizes[i] == BB * IC * NV * HH * WW)  x = (const float*)d_in[i];
        else if (wn < 4)                                 w[wn++] = (const float*)d_in[i];
    }
    float* out = (float*)d_out;

    k0_tables<<<8, 256>>>();
    k1_fwd_w<<<3072, 128>>>(x);
    k2_fwd_h<<<384, 256>>>();
    k3a_time<<<dim3(96, 4), 128>>>(t, w[0], w[1], w[2], w[3]);
    k3b_mix<<<768, 256>>>();
    k4_inv_h<<<384, 256>>>();
    k5_inv_w<<<3072, 256>>>(out);
}

// round 11
// speedup vs baseline: 1.5623x; 1.0726x over previous
#include <cuda_runtime.h>
#include <cuda_bf16.h>
#include <cstdint>
#include <cstddef>

#define BB 16
#define IC 8
#define OC 8
#define NV 3
#define HH 256
#define WW 256
#define M1 16
#define M2 16
#define TD 256

// -------------------- static scratch (no runtime allocation) --------------------
__device__ __align__(16) float2 g_Y[BB*IC*NV*HH*16];      // fwd DFT over w
__device__ __align__(16) float2 g_X[BB*IC*NV*32*16];      // fwd modes
__device__ __align__(16) float  g_TW[4*BB*(IC*OC*NV*M1*M2)]; // time-contracted weights
__device__ __align__(16) float2 g_G[BB*OC*NV*32*16];      // mixed modes
__device__ __align__(16) float2 g_Z[BB*OC*NV*HH*16];      // inv DFT over h
__device__ __align__(16) float  g_T5c[2048];              // [kw][w]: cos * al
__device__ __align__(16) float  g_T5s[2048];              // [kw][w]: sin * al

// ---------------------------------------------------------------------------
// k0: k5-stage twiddle tables, once per launch. 8 x 256 threads.
// ---------------------------------------------------------------------------
__global__ __launch_bounds__(256) void k0_tables() {
    const int idx = blockIdx.x * 256 + threadIdx.x;    // 0..2047
    int kw = idx >> 7, w = idx & 127;
    float sn, cs;
    sincospif((float)(kw * w) * (1.0f / 128.0f), &sn, &cs);
    float al = ((kw == 0) ? 1.0f : 2.0f) * (1.0f / 65536.0f);
    g_T5c[idx] = cs * al;
    g_T5s[idx] = sn * al;
}

// ---------------------------------------------------------------------------
// k1: forward DFT over w (r10 version, UNCHANGED).
// ---------------------------------------------------------------------------
#define K1_STRIDE 132
#define K1_DIFOFF (32 * K1_STRIDE + 16)
__global__ __launch_bounds__(128) void k1_fwd_w(const float* __restrict__ x) {
    __shared__ float sbuf[K1_DIFOFF + 32 * K1_STRIDE];
    const int tid = threadIdx.x;

    const float4* xg = (const float4*)(x + (size_t)blockIdx.x * (32 * 256));
#pragma unroll
    for (int j = 0; j < 8; j++) {
        int p = j * 128 + tid;
        int row = p >> 5, c4 = p & 31;
        float4 a = xg[row * 64 + c4];
        float4 b = xg[row * 64 + 32 + c4];
        *(float4*)&sbuf[row * K1_STRIDE + c4 * 4] =
            make_float4(a.x + b.x, a.y + b.y, a.z + b.z, a.w + b.w);
        *(float4*)&sbuf[K1_DIFOFF + row * K1_STRIDE + c4 * 4] =
            make_float4(a.x - b.x, a.y - b.y, a.z - b.z, a.w - b.w);
    }
    __syncthreads();

    const int k  = tid & 15;
    const int rg = tid >> 4;
    const float* base0 = sbuf + ((k & 1) ? K1_DIFOFF : 0) + rg * K1_STRIDE;

    float sn, cs;
    sincospif((float)k * (1.0f / 128.0f), &sn, &cs);
    const float stc = cs, sts = -sn;
    float pc = 1.0f, ps = 0.0f;

    float ar0 = 0, ai0 = 0, ar1 = 0, ai1 = 0, ar2 = 0, ai2 = 0, ar3 = 0, ai3 = 0;
#pragma unroll 4
    for (int w = 0; w < 128; w++) {
        float u0 = base0[w];
        float u1 = base0[ 8 * K1_STRIDE + w];
        float u2 = base0[16 * K1_STRIDE + w];
        float u3 = base0[24 * K1_STRIDE + w];
        ar0 += u0 * pc; ai0 += u0 * ps;
        ar1 += u1 * pc; ai1 += u1 * ps;
        ar2 += u2 * pc; ai2 += u2 * ps;
        ar3 += u3 * pc; ai3 += u3 * ps;
        float npc = pc * stc - ps * sts;
        float nps = pc * sts + ps * stc;
        pc = npc; ps = nps;
    }

    size_t rowbase = (size_t)blockIdx.x * 32;
    g_Y[(rowbase + rg     ) * 16 + k] = make_float2(ar0, ai0);
    g_Y[(rowbase + rg +  8) * 16 + k] = make_float2(ar1, ai1);
    g_Y[(rowbase + rg + 16) * 16 + k] = make_float2(ar2, ai2);
    g_Y[(rowbase + rg + 24) * 16 + k] = make_float2(ar3, ai3);
}

// ---------------------------------------------------------------------------
// k2: forward DFT over h (round-3 version, UNCHANGED). Grid 384 x 256.
// ---------------------------------------------------------------------------
__global__ __launch_bounds__(256) void k2_fwd_h() {
    __shared__ float2 sy[4096];   // [h][kw]
    const int tid = threadIdx.x;

    const float4* yg = (const float4*)(g_Y + (size_t)blockIdx.x * 4096);
    float4* sy4 = (float4*)sy;
#pragma unroll
    for (int it = 0; it < 8; it++)
        sy4[it * 256 + tid] = yg[it * 256 + tid];
    __syncthreads();

#pragma unroll
    for (int p = tid; p < 2048; p += 256) {
        int h = p >> 4, kw = p & 15;
        float2 a = sy[h * 16 + kw], b = sy[(h + 128) * 16 + kw];
        sy[h * 16 + kw]         = make_float2(a.x + b.x, a.y + b.y);
        sy[(h + 128) * 16 + kw] = make_float2(a.x - b.x, a.y - b.y);
    }
    __syncthreads();

    const int kw = tid & 15;
    const int s  = tid >> 4;
    const int hbase = (s & 1) << 7;

    float s1, c1, s2, c2;
    sincospif((float)s * (1.0f / 128.0f), &s1, &c1);
    sincospif((float)(s - 16) * (1.0f / 128.0f), &s2, &c2);
    const float st1c = c1, st1s = -s1;
    const float st2c = c2, st2s = -s2;
    float p1c = 1, p1s = 0, p2c = 1, p2s = 0;
    float a1r = 0, a1i = 0, a2r = 0, a2i = 0;

#pragma unroll 4
    for (int h = 0; h < 128; h++) {
        float2 u = sy[(hbase + h) * 16 + kw];
        a1r += u.x * p1c - u.y * p1s;
        a1i += u.x * p1s + u.y * p1c;
        a2r += u.x * p2c - u.y * p2s;
        a2i += u.x * p2s + u.y * p2c;
        float n;
        n = p1c * st1c - p1s * st1s; p1s = p1c * st1s + p1s * st1c; p1c = n;
        n = p2c * st2c - p2s * st2s; p2s = p2c * st2s + p2s * st2c; p2c = n;
    }

    size_t ob = (size_t)blockIdx.x * 512;
    g_X[ob + s * 16 + kw]        = make_float2(a1r, a1i);
    g_X[ob + (16 + s) * 16 + kw] = make_float2(a2r, a2i);
}

// ---------------------------------------------------------------------------
// k3a: time contraction via tf32 tensor cores.
// out[arr][b][row] = sum_k W[row,k] * t[b,k]   (GEMM: M=196608, N=16, K=256)
// Block: 256 threads (8 warps), 128 rows. K staged in 8 chunks of 32 into
// smem (row stride 36 -> conflict-free A-fragment reads). t staged once as
// two [k][8] tf32 arrays (stride 8 -> conflict-free B-fragment reads).
// mma.sync.m16n8k8.tf32; operands rounded with cvt.rna. Grid: 1536.
// ---------------------------------------------------------------------------
__device__ __forceinline__ unsigned f2tf32(float f) {
    unsigned u;
    asm("cvt.rna.tf32.f32 %0, %1;" : "=r"(u) : "f"(f));
    return u;
}

__global__ __launch_bounds__(256) void k3a_time_mma(const float* __restrict__ t,
                                                    const float* __restrict__ wa,
                                                    const float* __restrict__ wb,
                                                    const float* __restrict__ wc,
                                                    const float* __restrict__ wd) {
    __shared__ unsigned Ws[128 * 36];      // [row][k-chunk 32 + pad 4]
    __shared__ unsigned tsB0[256 * 8];     // [k][b]   b=0..7
    __shared__ unsigned tsB1[256 * 8];     // [k][b-8] b=8..15
    const int tid  = threadIdx.x;
    const int warp = tid >> 5;
    const int lane = tid & 31;
    const int g    = lane >> 2;     // groupID 0..7
    const int tg   = lane & 3;      // thread-in-group 0..3

    // stage t (once): 4096 elems
#pragma unroll
    for (int j = 0; j < 16; j++) {
        int idx = j * 256 + tid;            // 0..4095
        int k = idx & 255, b = idx >> 8;
        unsigned v = f2tf32(t[b * 256 + k]);
        if (b < 8) tsB0[k * 8 + b] = v;
        else       tsB1[k * 8 + (b - 8)] = v;
    }

    const int arr  = blockIdx.x / 384;            // 0..3 (wa..wd)
    const int row0 = (blockIdx.x % 384) * 128;    // row within array
    const float* W = (arr == 0) ? wa : (arr == 1) ? wb : (arr == 2) ? wc : wd;
    float* out = g_TW + (size_t)arr * (16 * 49152);

    float d0[2][4];
#pragma unroll
    for (int nt = 0; nt < 2; nt++)
#pragma unroll
        for (int e = 0; e < 4; e++) d0[nt][e] = 0.0f;

    const int rowW = row0 + warp * 16;   // this warp's 16-row tile

#pragma unroll 1
    for (int c = 0; c < 8; c++) {
        __syncthreads();
        // stage 128 rows x 32 k (coalesced: each 128B row-chunk = 1 line)
#pragma unroll
        for (int j = 0; j < 4; j++) {
            int idx = j * 256 + tid;          // 0..1023 float4 slots
            int rr = idx >> 3, q = idx & 7;
            float4 v = *(const float4*)(W + (size_t)(row0 + rr) * 256 + c * 32 + q * 4);
            unsigned* dst = &Ws[rr * 36 + q * 4];
            dst[0] = f2tf32(v.x); dst[1] = f2tf32(v.y);
            dst[2] = f2tf32(v.z); dst[3] = f2tf32(v.w);
        }
        __syncthreads();

#pragma unroll
        for (int ks = 0; ks < 4; ks++) {
            // A fragment: rows (warp*16+g, +8), cols ks*8 + tg (+4)
            const unsigned* ab = &Ws[(warp * 16 + g) * 36 + ks * 8 + tg];
            unsigned a0 = ab[0];
            unsigned a1 = ab[8 * 36];
            unsigned a2 = ab[4];
            unsigned a3 = ab[8 * 36 + 4];
            int kg = c * 32 + ks * 8;
            // B fragments: (k = kg+tg, n=g) and (k = kg+tg+4, n=g)
            unsigned b00 = tsB0[(kg + tg) * 8 + g];
            unsigned b01 = tsB0[(kg + tg + 4) * 8 + g];
            unsigned b10 = tsB1[(kg + tg) * 8 + g];
            unsigned b11 = tsB1[(kg + tg + 4) * 8 + g];

            asm volatile(
                "mma.sync.aligned.m16n8k8.row.col.f32.tf32.tf32.f32 "
                "{%0,%1,%2,%3}, {%4,%5,%6,%7}, {%8,%9}, {%0,%1,%2,%3};"
                : "+f"(d0[0][0]), "+f"(d0[0][1]), "+f"(d0[0][2]), "+f"(d0[0][3])
                : "r"(a0), "r"(a1), "r"(a2), "r"(a3), "r"(b00), "r"(b01));
            asm volatile(
                "mma.sync.aligned.m16n8k8.row.col.f32.tf32.tf32.f32 "
                "{%0,%1,%2,%3}, {%4,%5,%6,%7}, {%8,%9}, {%0,%1,%2,%3};"
                : "+f"(d0[1][0]), "+f"(d0[1][1]), "+f"(d0[1][2]), "+f"(d0[1][3])
                : "r"(a0), "r"(a1), "r"(a2), "r"(a3), "r"(b10), "r"(b11));
        }
    }

    // epilogue: D layout c0:(g, 2tg) c1:(g, 2tg+1) c2:(g+8, 2tg) c3:(g+8, 2tg+1)
#pragma unroll
    for (int nt = 0; nt < 2; nt++) {
        int bb = nt * 8 + 2 * tg;
        out[(size_t)bb       * 49152 + rowW + g]     = d0[nt][0];
        out[(size_t)(bb + 1) * 49152 + rowW + g]     = d0[nt][1];
        out[(size_t)bb       * 49152 + rowW + 8 + g] = d0[nt][2];
        out[(size_t)(bb + 1) * 49152 + rowW + 8 + g] = d0[nt][3];
    }
}

// ---------------------------------------------------------------------------
// k3b: spectral mixing over IC (round-3 version, UNCHANGED). Grid: 768 x 256.
// ---------------------------------------------------------------------------
__global__ __launch_bounds__(256) void k3b_mix() {
    const int gtid = blockIdx.x * 256 + threadIdx.x;
    const int kw = gtid & 15;
    int r = gtid >> 4;
    const int s = r & 31; r >>= 5;
    const int v = r % 3;  r /= 3;
    const int o = r & 7;
    const int b = r >> 3;

    const int arrbase = (s < 16) ? 0 : 2;
    const int y = s & 15;
    const float* TR = g_TW + (size_t)(arrbase * 16 + b) * 49152;
    const float* TI = g_TW + (size_t)((arrbase + 1) * 16 + b) * 49152;

    float gr = 0.0f, gi = 0.0f;
#pragma unroll
    for (int i = 0; i < 8; i++) {
        float2 xf = g_X[((size_t)((b * 8 + i) * 3 + v) * 32 + s) * 16 + kw];
        int row = (((i * 8 + o) * 3 + v) * 16 + y) * 16 + kw;
        float wr = TR[row], wi = TI[row];
        gr += xf.x * wr - xf.y * wi;
        gi += xf.x * wi + xf.y * wr;
    }
    g_G[gtid] = make_float2(gr, gi);
}

// ---------------------------------------------------------------------------
// k4: inverse DFT over h (UNCHANGED from r10).
// ---------------------------------------------------------------------------
__global__ __launch_bounds__(256) void k4_inv_h() {
    __shared__ float2 Gs[512];
    const int tid = threadIdx.x;
    ((float4*)Gs)[tid] = ((const float4*)(g_G + (size_t)blockIdx.x * 512))[tid];
    __syncthreads();

    const int h = tid & 127;
    const int half = tid >> 7;

    float AR[8], AI[8], BR[8], BI[8];
#pragma unroll
    for (int q = 0; q < 8; q++) { AR[q] = AI[q] = BR[q] = BI[q] = 0.0f; }

    float stc, sts;
    sincospif((float)h * (1.0f / 128.0f), &sts, &stc);
    float pc = 1.0f, ps = 0.0f;

#pragma unroll 1
    for (int sl = 0; sl < 32; sl++) {
        if (sl == 16) { ps = -ps; }
        const float4* gp = (const float4*)&Gs[sl * 16 + half * 8];
        if ((sl & 1) == 0) {
#pragma unroll
            for (int q4 = 0; q4 < 4; q4++) {
                float4 g = gp[q4];
                AR[2*q4]   += g.x * pc - g.y * ps;
                AI[2*q4]   += g.x * ps + g.y * pc;
                AR[2*q4+1] += g.z * pc - g.w * ps;
                AI[2*q4+1] += g.z * ps + g.w * pc;
            }
        } else {
#pragma unroll
            for (int q4 = 0; q4 < 4; q4++) {
                float4 g = gp[q4];
                BR[2*q4]   += g.x * pc - g.y * ps;
                BI[2*q4]   += g.x * ps + g.y * pc;
                BR[2*q4+1] += g.z * pc - g.w * ps;
                BI[2*q4+1] += g.z * ps + g.w * pc;
            }
        }
        float n = pc * stc - ps * sts;
        ps = pc * sts + ps * stc; pc = n;
    }

    float4* zlo = (float4*)(g_Z + (size_t)blockIdx.x * 4096 + h * 16 + half * 8);
    float4* zhi = (float4*)(g_Z + (size_t)blockIdx.x * 4096 + (h + 128) * 16 + half * 8);
#pragma unroll
    for (int q = 0; q < 4; q++) {
        zlo[q] = make_float4(AR[2*q] + BR[2*q], AI[2*q] + BI[2*q],
                             AR[2*q+1] + BR[2*q+1], AI[2*q+1] + BI[2*q+1]);
        zhi[q] = make_float4(AR[2*q] - BR[2*q], AI[2*q] - BI[2*q],
                             AR[2*q+1] - BR[2*q+1], AI[2*q+1] - BI[2*q+1]);
    }
}

// ---------------------------------------------------------------------------
// k5: inverse real DFT over w (UNCHANGED from r10). Grid 3072.
// ---------------------------------------------------------------------------
__global__ __launch_bounds__(256) void k5_inv_w(float* __restrict__ out) {
    __shared__ float Ct[16 * 128];
    __shared__ float St[16 * 128];
    __shared__ float2 Zs[512];
    const int tid = threadIdx.x;

    {
        float4* c4 = (float4*)Ct; const float4* gc = (const float4*)g_T5c;
        float4* s4 = (float4*)St; const float4* gs = (const float4*)g_T5s;
#pragma unroll
        for (int j = 0; j < 2; j++) {
            c4[j * 256 + tid] = gc[j * 256 + tid];
            s4[j * 256 + tid] = gs[j * 256 + tid];
        }
    }
    ((float4*)Zs)[tid] = ((const float4*)(g_Z + (size_t)blockIdx.x * 512))[tid];
    __syncthreads();

    const int r  = tid >> 3;
    const int wb = tid & 7;

    float A[16], B[16];
#pragma unroll
    for (int u = 0; u < 16; u++) { A[u] = 0.0f; B[u] = 0.0f; }

#pragma unroll
    for (int kwv = 0; kwv < 16; kwv++) {
        float2 z = Zs[r * 16 + kwv];
#pragma unroll
        for (int u4 = 0; u4 < 4; u4++) {
            float4 c4 = *(const float4*)&Ct[kwv * 128 + wb * 16 + u4 * 4];
            float4 s4 = *(const float4*)&St[kwv * 128 + wb * 16 + u4 * 4];
            float* T = ((kwv & 1) == 0) ? A : B;
            T[u4 * 4 + 0] += z.x * c4.x - z.y * s4.x;
            T[u4 * 4 + 1] += z.x * c4.y - z.y * s4.y;
            T[u4 * 4 + 2] += z.x * c4.z - z.y * s4.z;
            T[u4 * 4 + 3] += z.x * c4.w - z.y * s4.w;
        }
    }

    float* orow = out + (size_t)blockIdx.x * (32 * 256) + r * 256 + wb * 16;
#pragma unroll
    for (int u4 = 0; u4 < 4; u4++) {
        float4 lo = make_float4(A[u4*4+0] + B[u4*4+0], A[u4*4+1] + B[u4*4+1],
                                A[u4*4+2] + B[u4*4+2], A[u4*4+3] + B[u4*4+3]);
        float4 hi = make_float4(A[u4*4+0] - B[u4*4+0], A[u4*4+1] - B[u4*4+1],
                                A[u4*4+2] - B[u4*4+2], A[u4*4+3] - B[u4*4+3]);
        *(float4*)&orow[u4 * 4]       = lo;
        *(float4*)&orow[128 + u4 * 4] = hi;
    }
}

// ---------------------------------------------------------------------------
extern "C" void kernel_launch(void* const* d_in, const int* in_sizes, int n_in,
                              void* d_out, int out_size) {
    const float* t = nullptr;
    const float* x = nullptr;
    const float* w[4] = {nullptr, nullptr, nullptr, nullptr};
    int wn = 0;
    for (int i = 0; i < n_in; i++) {
        if (in_sizes[i] == BB * TD)                      t = (const float*)d_in[i];
        else if (in_sizes[i] == BB * IC * NV * HH * WW)  x = (const float*)d_in[i];
        else if (wn < 4)                                 w[wn++] = (const float*)d_in[i];
    }
    float* out = (float*)d_out;

    k0_tables<<<8, 256>>>();
    k1_fwd_w<<<3072, 128>>>(x);
    k2_fwd_h<<<384, 256>>>();
    k3a_time_mma<<<1536, 256>>>(t, w[0], w[1], w[2], w[3]);
    k3b_mix<<<768, 256>>>();
    k4_inv_h<<<384, 256>>>();
    k5_inv_w<<<3072, 256>>>(out);
}

// round 12
// speedup vs baseline: 1.5902x; 1.0179x over previous
#include <cuda_runtime.h>
#include <cuda_bf16.h>
#include <cstdint>
#include <cstddef>

#define BB 16
#define IC 8
#define OC 8
#define NV 3
#define HH 256
#define WW 256
#define M1 16
#define M2 16
#define TD 256

// -------------------- static scratch (no runtime allocation) --------------------
__device__ __align__(16) float2 g_Y[BB*IC*NV*HH*16];      // fwd DFT over w
__device__ __align__(16) float2 g_X[BB*IC*NV*32*16];      // fwd modes
__device__ __align__(16) float  g_TW[4*BB*(IC*OC*NV*M1*M2)]; // time-contracted weights
__device__ __align__(16) float2 g_G[BB*OC*NV*32*16];      // mixed modes
__device__ __align__(16) float2 g_Z[BB*OC*NV*HH*16];      // inv DFT over h
__device__ __align__(16) float  g_T5c[2048];              // [kw][w]: cos * al
__device__ __align__(16) float  g_T5s[2048];              // [kw][w]: sin * al
__device__ __align__(16) unsigned g_T1m[256*32];          // [w][c]: tf32 twiddles, c=2k:cos, 2k+1:-sin

__device__ __forceinline__ unsigned f2tf32(float f) {
    unsigned u;
    asm("cvt.rna.tf32.f32 %0, %1;" : "=r"(u) : "f"(f));
    return u;
}

// ---------------------------------------------------------------------------
// k0: twiddle tables, once per launch. 32 x 256 threads.
// ---------------------------------------------------------------------------
__global__ __launch_bounds__(256) void k0_tables() {
    const int idx = blockIdx.x * 256 + threadIdx.x;    // 0..8191
    if (idx < 2048) {
        int kw = idx >> 7, w = idx & 127;
        float sn, cs;
        sincospif((float)(kw * w) * (1.0f / 128.0f), &sn, &cs);
        float al = ((kw == 0) ? 1.0f : 2.0f) * (1.0f / 65536.0f);
        g_T5c[idx] = cs * al;
        g_T5s[idx] = sn * al;
    }
    // k1 MMA B-matrix: [w][32]; col 2k = cos(2pi k w/256), col 2k+1 = -sin
    {
        int w = idx >> 5, c = idx & 31;
        int k = c >> 1;
        float sn, cs;
        sincospif((float)(k * w) * (1.0f / 128.0f), &sn, &cs);
        g_T1m[idx] = f2tf32((c & 1) ? -sn : cs);
    }
}

// ---------------------------------------------------------------------------
// k1: forward DFT over w via tf32 tensor cores.
// Y[row][k] (cplx) = sum_w x[row][w] * e^{-2pi i k w/256}
// GEMM: M=98304, K=256, N=32 (16 modes x re/im packed as B cols).
// Fragment layouts identical to the validated k3a_time_mma. Grid: 768 x 256.
// ---------------------------------------------------------------------------
__global__ __launch_bounds__(256) void k1_mma(const float* __restrict__ x) {
    __shared__ unsigned Ws[128 * 36];      // A chunk: 128 rows x 32 w (+pad)
    __shared__ unsigned Ts[4][32 * 8];     // B chunk: 4 n-groups x [w][8]
    const int tid  = threadIdx.x;
    const int warp = tid >> 5;
    const int lane = tid & 31;
    const int g    = lane >> 2;
    const int tg   = lane & 3;
    const int row0 = blockIdx.x * 128;

    float d[4][4];
#pragma unroll
    for (int j = 0; j < 4; j++)
#pragma unroll
        for (int e = 0; e < 4; e++) d[j][e] = 0.0f;

#pragma unroll 1
    for (int c = 0; c < 8; c++) {
        __syncthreads();
        // stage A: 128 rows x 32 w, coalesced
#pragma unroll
        for (int j = 0; j < 4; j++) {
            int idx = j * 256 + tid;          // 0..1023 float4 slots
            int rr = idx >> 3, q = idx & 7;
            float4 v = *(const float4*)(x + (size_t)(row0 + rr) * 256 + c * 32 + q * 4);
            unsigned* dst = &Ws[rr * 36 + q * 4];
            dst[0] = f2tf32(v.x); dst[1] = f2tf32(v.y);
            dst[2] = f2tf32(v.z); dst[3] = f2tf32(v.w);
        }
        // stage B chunk: 32 w x 32 cols
#pragma unroll
        for (int j = 0; j < 4; j++) {
            int idx = j * 256 + tid;          // 0..1023
            int ww = idx >> 5, cc = idx & 31;
            Ts[cc >> 3][ww * 8 + (cc & 7)] = g_T1m[(c * 32 + ww) * 32 + cc];
        }
        __syncthreads();

#pragma unroll
        for (int ks = 0; ks < 4; ks++) {
            const unsigned* ab = &Ws[(warp * 16 + g) * 36 + ks * 8 + tg];
            unsigned a0 = ab[0];
            unsigned a1 = ab[8 * 36];
            unsigned a2 = ab[4];
            unsigned a3 = ab[8 * 36 + 4];
            int kg = ks * 8;
#pragma unroll
            for (int j = 0; j < 4; j++) {
                unsigned b0 = Ts[j][(kg + tg) * 8 + g];
                unsigned b1 = Ts[j][(kg + tg + 4) * 8 + g];
                asm volatile(
                    "mma.sync.aligned.m16n8k8.row.col.f32.tf32.tf32.f32 "
                    "{%0,%1,%2,%3}, {%4,%5,%6,%7}, {%8,%9}, {%0,%1,%2,%3};"
                    : "+f"(d[j][0]), "+f"(d[j][1]), "+f"(d[j][2]), "+f"(d[j][3])
                    : "r"(a0), "r"(a1), "r"(a2), "r"(a3), "r"(b0), "r"(b1));
            }
        }
    }

    // epilogue: n8-tile j, cols (2tg, 2tg+1) -> complex mode k = 4j + tg
    const int rowW = row0 + warp * 16;
#pragma unroll
    for (int j = 0; j < 4; j++) {
        int k = j * 4 + tg;
        g_Y[(size_t)(rowW + g)     * 16 + k] = make_float2(d[j][0], d[j][1]);
        g_Y[(size_t)(rowW + 8 + g) * 16 + k] = make_float2(d[j][2], d[j][3]);
    }
}

// ---------------------------------------------------------------------------
// k2: forward DFT over h (round-3 version, UNCHANGED). Grid 384 x 256.
// ---------------------------------------------------------------------------
__global__ __launch_bounds__(256) void k2_fwd_h() {
    __shared__ float2 sy[4096];   // [h][kw]
    const int tid = threadIdx.x;

    const float4* yg = (const float4*)(g_Y + (size_t)blockIdx.x * 4096);
    float4* sy4 = (float4*)sy;
#pragma unroll
    for (int it = 0; it < 8; it++)
        sy4[it * 256 + tid] = yg[it * 256 + tid];
    __syncthreads();

#pragma unroll
    for (int p = tid; p < 2048; p += 256) {
        int h = p >> 4, kw = p & 15;
        float2 a = sy[h * 16 + kw], b = sy[(h + 128) * 16 + kw];
        sy[h * 16 + kw]         = make_float2(a.x + b.x, a.y + b.y);
        sy[(h + 128) * 16 + kw] = make_float2(a.x - b.x, a.y - b.y);
    }
    __syncthreads();

    const int kw = tid & 15;
    const int s  = tid >> 4;
    const int hbase = (s & 1) << 7;

    float s1, c1, s2, c2;
    sincospif((float)s * (1.0f / 128.0f), &s1, &c1);
    sincospif((float)(s - 16) * (1.0f / 128.0f), &s2, &c2);
    const float st1c = c1, st1s = -s1;
    const float st2c = c2, st2s = -s2;
    float p1c = 1, p1s = 0, p2c = 1, p2s = 0;
    float a1r = 0, a1i = 0, a2r = 0, a2i = 0;

#pragma unroll 4
    for (int h = 0; h < 128; h++) {
        float2 u = sy[(hbase + h) * 16 + kw];
        a1r += u.x * p1c - u.y * p1s;
        a1i += u.x * p1s + u.y * p1c;
        a2r += u.x * p2c - u.y * p2s;
        a2i += u.x * p2s + u.y * p2c;
        float n;
        n = p1c * st1c - p1s * st1s; p1s = p1c * st1s + p1s * st1c; p1c = n;
        n = p2c * st2c - p2s * st2s; p2s = p2c * st2s + p2s * st2c; p2c = n;
    }

    size_t ob = (size_t)blockIdx.x * 512;
    g_X[ob + s * 16 + kw]        = make_float2(a1r, a1i);
    g_X[ob + (16 + s) * 16 + kw] = make_float2(a2r, a2i);
}

// ---------------------------------------------------------------------------
// k3a: time contraction via tf32 tensor cores (r11 version, UNCHANGED).
// ---------------------------------------------------------------------------
__global__ __launch_bounds__(256) void k3a_time_mma(const float* __restrict__ t,
                                                    const float* __restrict__ wa,
                                                    const float* __restrict__ wb,
                                                    const float* __restrict__ wc,
                                                    const float* __restrict__ wd) {
    __shared__ unsigned Ws[128 * 36];
    __shared__ unsigned tsB0[256 * 8];
    __shared__ unsigned tsB1[256 * 8];
    const int tid  = threadIdx.x;
    const int warp = tid >> 5;
    const int lane = tid & 31;
    const int g    = lane >> 2;
    const int tg   = lane & 3;

#pragma unroll
    for (int j = 0; j < 16; j++) {
        int idx = j * 256 + tid;
        int k = idx & 255, b = idx >> 8;
        unsigned v = f2tf32(t[b * 256 + k]);
        if (b < 8) tsB0[k * 8 + b] = v;
        else       tsB1[k * 8 + (b - 8)] = v;
    }

    const int arr  = blockIdx.x / 384;
    const int row0 = (blockIdx.x % 384) * 128;
    const float* W = (arr == 0) ? wa : (arr == 1) ? wb : (arr == 2) ? wc : wd;
    float* out = g_TW + (size_t)arr * (16 * 49152);

    float d0[2][4];
#pragma unroll
    for (int nt = 0; nt < 2; nt++)
#pragma unroll
        for (int e = 0; e < 4; e++) d0[nt][e] = 0.0f;

    const int rowW = row0 + warp * 16;

#pragma unroll 1
    for (int c = 0; c < 8; c++) {
        __syncthreads();
#pragma unroll
        for (int j = 0; j < 4; j++) {
            int idx = j * 256 + tid;
            int rr = idx >> 3, q = idx & 7;
            float4 v = *(const float4*)(W + (size_t)(row0 + rr) * 256 + c * 32 + q * 4);
            unsigned* dst = &Ws[rr * 36 + q * 4];
            dst[0] = f2tf32(v.x); dst[1] = f2tf32(v.y);
            dst[2] = f2tf32(v.z); dst[3] = f2tf32(v.w);
        }
        __syncthreads();

#pragma unroll
        for (int ks = 0; ks < 4; ks++) {
            const unsigned* ab = &Ws[(warp * 16 + g) * 36 + ks * 8 + tg];
            unsigned a0 = ab[0];
            unsigned a1 = ab[8 * 36];
            unsigned a2 = ab[4];
            unsigned a3 = ab[8 * 36 + 4];
            int kg = c * 32 + ks * 8;
            unsigned b00 = tsB0[(kg + tg) * 8 + g];
            unsigned b01 = tsB0[(kg + tg + 4) * 8 + g];
            unsigned b10 = tsB1[(kg + tg) * 8 + g];
            unsigned b11 = tsB1[(kg + tg + 4) * 8 + g];

            asm volatile(
                "mma.sync.aligned.m16n8k8.row.col.f32.tf32.tf32.f32 "
                "{%0,%1,%2,%3}, {%4,%5,%6,%7}, {%8,%9}, {%0,%1,%2,%3};"
                : "+f"(d0[0][0]), "+f"(d0[0][1]), "+f"(d0[0][2]), "+f"(d0[0][3])
                : "r"(a0), "r"(a1), "r"(a2), "r"(a3), "r"(b00), "r"(b01));
            asm volatile(
                "mma.sync.aligned.m16n8k8.row.col.f32.tf32.tf32.f32 "
                "{%0,%1,%2,%3}, {%4,%5,%6,%7}, {%8,%9}, {%0,%1,%2,%3};"
                : "+f"(d0[1][0]), "+f"(d0[1][1]), "+f"(d0[1][2]), "+f"(d0[1][3])
                : "r"(a0), "r"(a1), "r"(a2), "r"(a3), "r"(b10), "r"(b11));
        }
    }

#pragma unroll
    for (int nt = 0; nt < 2; nt++) {
        int bb = nt * 8 + 2 * tg;
        out[(size_t)bb       * 49152 + rowW + g]     = d0[nt][0];
        out[(size_t)(bb + 1) * 49152 + rowW + g]     = d0[nt][1];
        out[(size_t)bb       * 49152 + rowW + 8 + g] = d0[nt][2];
        out[(size_t)(bb + 1) * 49152 + rowW + 8 + g] = d0[nt][3];
    }
}

// ---------------------------------------------------------------------------
// k3b: spectral mixing over IC (UNCHANGED). Grid: 768 x 256.
// ---------------------------------------------------------------------------
__global__ __launch_bounds__(256) void k3b_mix() {
    const int gtid = blockIdx.x * 256 + threadIdx.x;
    const int kw = gtid & 15;
    int r = gtid >> 4;
    const int s = r & 31; r >>= 5;
    const int v = r % 3;  r /= 3;
    const int o = r & 7;
    const int b = r >> 3;

    const int arrbase = (s < 16) ? 0 : 2;
    const int y = s & 15;
    const float* TR = g_TW + (size_t)(arrbase * 16 + b) * 49152;
    const float* TI = g_TW + (size_t)((arrbase + 1) * 16 + b) * 49152;

    float gr = 0.0f, gi = 0.0f;
#pragma unroll
    for (int i = 0; i < 8; i++) {
        float2 xf = g_X[((size_t)((b * 8 + i) * 3 + v) * 32 + s) * 16 + kw];
        int row = (((i * 8 + o) * 3 + v) * 16 + y) * 16 + kw;
        float wr = TR[row], wi = TI[row];
        gr += xf.x * wr - xf.y * wi;
        gi += xf.x * wi + xf.y * wr;
    }
    g_G[gtid] = make_float2(gr, gi);
}

// ---------------------------------------------------------------------------
// k4: inverse DFT over h (UNCHANGED).
// ---------------------------------------------------------------------------
__global__ __launch_bounds__(256) void k4_inv_h() {
    __shared__ float2 Gs[512];
    const int tid = threadIdx.x;
    ((float4*)Gs)[tid] = ((const float4*)(g_G + (size_t)blockIdx.x * 512))[tid];
    __syncthreads();

    const int h = tid & 127;
    const int half = tid >> 7;

    float AR[8], AI[8], BR[8], BI[8];
#pragma unroll
    for (int q = 0; q < 8; q++) { AR[q] = AI[q] = BR[q] = BI[q] = 0.0f; }

    float stc, sts;
    sincospif((float)h * (1.0f / 128.0f), &sts, &stc);
    float pc = 1.0f, ps = 0.0f;

#pragma unroll 1
    for (int sl = 0; sl < 32; sl++) {
        if (sl == 16) { ps = -ps; }
        const float4* gp = (const float4*)&Gs[sl * 16 + half * 8];
        if ((sl & 1) == 0) {
#pragma unroll
            for (int q4 = 0; q4 < 4; q4++) {
                float4 g = gp[q4];
                AR[2*q4]   += g.x * pc - g.y * ps;
                AI[2*q4]   += g.x * ps + g.y * pc;
                AR[2*q4+1] += g.z * pc - g.w * ps;
                AI[2*q4+1] += g.z * ps + g.w * pc;
            }
        } else {
#pragma unroll
            for (int q4 = 0; q4 < 4; q4++) {
                float4 g = gp[q4];
                BR[2*q4]   += g.x * pc - g.y * ps;
                BI[2*q4]   += g.x * ps + g.y * pc;
                BR[2*q4+1] += g.z * pc - g.w * ps;
                BI[2*q4+1] += g.z * ps + g.w * pc;
            }
        }
        float n = pc * stc - ps * sts;
        ps = pc * sts + ps * stc; pc = n;
    }

    float4* zlo = (float4*)(g_Z + (size_t)blockIdx.x * 4096 + h * 16 + half * 8);
    float4* zhi = (float4*)(g_Z + (size_t)blockIdx.x * 4096 + (h + 128) * 16 + half * 8);
#pragma unroll
    for (int q = 0; q < 4; q++) {
        zlo[q] = make_float4(AR[2*q] + BR[2*q], AI[2*q] + BI[2*q],
                             AR[2*q+1] + BR[2*q+1], AI[2*q+1] + BI[2*q+1]);
        zhi[q] = make_float4(AR[2*q] - BR[2*q], AI[2*q] - BI[2*q],
                             AR[2*q+1] - BR[2*q+1], AI[2*q+1] - BI[2*q+1]);
    }
}

// ---------------------------------------------------------------------------
// k5: inverse real DFT over w (UNCHANGED). Grid 3072.
// ---------------------------------------------------------------------------
__global__ __launch_bounds__(256) void k5_inv_w(float* __restrict__ out) {
    __shared__ float Ct[16 * 128];
    __shared__ float St[16 * 128];
    __shared__ float2 Zs[512];
    const int tid = threadIdx.x;

    {
        float4* c4 = (float4*)Ct; const float4* gc = (const float4*)g_T5c;
        float4* s4 = (float4*)St; const float4* gs = (const float4*)g_T5s;
#pragma unroll
        for (int j = 0; j < 2; j++) {
            c4[j * 256 + tid] = gc[j * 256 + tid];
            s4[j * 256 + tid] = gs[j * 256 + tid];
        }
    }
    ((float4*)Zs)[tid] = ((const float4*)(g_Z + (size_t)blockIdx.x * 512))[tid];
    __syncthreads();

    const int r  = tid >> 3;
    const int wb = tid & 7;

    float A[16], B[16];
#pragma unroll
    for (int u = 0; u < 16; u++) { A[u] = 0.0f; B[u] = 0.0f; }

#pragma unroll
    for (int kwv = 0; kwv < 16; kwv++) {
        float2 z = Zs[r * 16 + kwv];
#pragma unroll
        for (int u4 = 0; u4 < 4; u4++) {
            float4 c4 = *(const float4*)&Ct[kwv * 128 + wb * 16 + u4 * 4];
            float4 s4 = *(const float4*)&St[kwv * 128 + wb * 16 + u4 * 4];
            float* T = ((kwv & 1) == 0) ? A : B;
            T[u4 * 4 + 0] += z.x * c4.x - z.y * s4.x;
            T[u4 * 4 + 1] += z.x * c4.y - z.y * s4.y;
            T[u4 * 4 + 2] += z.x * c4.z - z.y * s4.z;
            T[u4 * 4 + 3] += z.x * c4.w - z.y * s4.w;
        }
    }

    float* orow = out + (size_t)blockIdx.x * (32 * 256) + r * 256 + wb * 16;
#pragma unroll
    for (int u4 = 0; u4 < 4; u4++) {
        float4 lo = make_float4(A[u4*4+0] + B[u4*4+0], A[u4*4+1] + B[u4*4+1],
                                A[u4*4+2] + B[u4*4+2], A[u4*4+3] + B[u4*4+3]);
        float4 hi = make_float4(A[u4*4+0] - B[u4*4+0], A[u4*4+1] - B[u4*4+1],
                                A[u4*4+2] - B[u4*4+2], A[u4*4+3] - B[u4*4+3]);
        *(float4*)&orow[u4 * 4]       = lo;
        *(float4*)&orow[128 + u4 * 4] = hi;
    }
}

// ---------------------------------------------------------------------------
extern "C" void kernel_launch(void* const* d_in, const int* in_sizes, int n_in,
                              void* d_out, int out_size) {
    const float* t = nullptr;
    const float* x = nullptr;
    const float* w[4] = {nullptr, nullptr, nullptr, nullptr};
    int wn = 0;
    for (int i = 0; i < n_in; i++) {
        if (in_sizes[i] == BB * TD)                      t = (const float*)d_in[i];
        else if (in_sizes[i] == BB * IC * NV * HH * WW)  x = (const float*)d_in[i];
        else if (wn < 4)                                 w[wn++] = (const float*)d_in[i];
    }
    float* out = (float*)d_out;

    k0_tables<<<32, 256>>>();
    k1_mma<<<768, 256>>>(x);
    k2_fwd_h<<<384, 256>>>();
    k3a_time_mma<<<1536, 256>>>(t, w[0], w[1], w[2], w[3]);
    k3b_mix<<<768, 256>>>();
    k4_inv_h<<<384, 256>>>();
    k5_inv_w<<<3072, 256>>>(out);
}